// round 12
// baseline (speedup 1.0000x reference)
#include <cuda_runtime.h>

#define NIMG 8
#define IMG  512
#define NPIX (IMG * IMG)

__device__ float g_min_a[NIMG * NPIX];
__device__ float g_min_b[NIMG * NPIX];
__device__ float g_max_a[NIMG * NPIX];
__device__ float g_max_b[NIMG * NPIX];

__device__ int g_flag[NIMG][4][2][64];
__device__ int g_headcnt[NIMG];

struct HeadConsts {
    float A2[32][18][2];
    float cb2[32][2];
    float w2[32];
    float Amin[32][9];
    float Amax[32][9];
    float Bsum[32][9];
    float b1[32];
    float b2;
};
__device__ HeadConsts HC;

template <bool M> __device__ __forceinline__ float xop(float a, float b) {
    return M ? fminf(a, b) : fmaxf(a, b);
}
template <bool M> __device__ __forceinline__ float xop3(float a, float b, float c) {
    return xop<M>(a, xop<M>(b, c));
}

__device__ __forceinline__ unsigned long long pk2(float lo, float hi) {
    unsigned long long r;
    asm("mov.b64 %0, {%1, %2};" : "=l"(r) : "f"(lo), "f"(hi));
    return r;
}
__device__ __forceinline__ void upk2(unsigned long long v, float& lo, float& hi) {
    asm("mov.b64 {%0, %1}, %2;" : "=f"(lo), "=f"(hi) : "l"(v));
}
__device__ __forceinline__ unsigned long long fma2(unsigned long long a, unsigned long long b,
                                                   unsigned long long c) {
    unsigned long long d;
    asm("fma.rn.f32x2 %0, %1, %2, %3;" : "=l"(d) : "l"(a), "l"(b), "l"(c));
    return d;
}

__device__ __forceinline__ void waitflag(int* p) {
    while (atomicAdd(p, 0) == 0) __nanosleep(64);
}

// ---- fold weights + zero DAG flags (runs fully before megakernel) ----------
__global__ void prep_kernel(const float* __restrict__ w0, const float* __restrict__ b0,
                            const float* __restrict__ w1, const float* __restrict__ b1,
                            const float* __restrict__ w2, const float* __restrict__ b2) {
    int id = threadIdx.x;
    if (id < 288) {
        int j = id / 9, t = id % 9;
        float amin = 0.f, amax = 0.f, bs = 0.f;
        for (int c = 0; c < 8; c++) {
            float w = w1[j * 72 + c * 9 + t];
            float w0c = w0[c];
            if (w0c >= 0.f) amin += w * w0c; else amax += w * w0c;
            bs += w * (65536.f * b0[c]);
        }
        HC.Amin[j][t] = amin; HC.Amax[j][t] = amax; HC.Bsum[j][t] = bs;
        HC.A2[j][t][0] = amin;     HC.A2[j][t][1] = amin;
        HC.A2[j][9 + t][0] = amax; HC.A2[j][9 + t][1] = amax;
    }
    if (id < 32) {
        int j = id;
        float cb = b1[j];
        for (int c = 0; c < 8; c++) {
            float bc = 65536.f * b0[c];
            for (int t = 0; t < 9; t++) cb += w1[j * 72 + c * 9 + t] * bc;
        }
        HC.cb2[j][0] = cb; HC.cb2[j][1] = cb;
        HC.w2[j] = w2[j];
        HC.b1[j] = b1[j];
    }
    if (id == 0) HC.b2 = b2[0];

    int* f = &g_flag[0][0][0][0];
    for (int i = id; i < NIMG * 4 * 2 * 64; i += blockDim.x) f[i] = 0;
    if (id < NIMG) g_headcnt[id] = 0;
}

// ---- round body (R4-proven): 16 rows x 4 cols/thread, 8 out rows -----------
template <bool M>
__device__ __forceinline__ float4 hpool16(float4 v, int r, int p, int warp, int lane,
                                          const float* eL, const float* eR, float BND) {
    float left  = __shfl_up_sync(0xffffffffu, v.w, 1);
    float right = __shfl_down_sync(0xffffffffu, v.x, 1);
    if (lane == 0)  left  = (warp == 0) ? BND : eR[((p * 4) + warp - 1) * 16 + r];
    if (lane == 31) right = (warp == 3) ? BND : eL[((p * 4) + warp + 1) * 16 + r];
    float mxy = xop<M>(v.x, v.y), mzw = xop<M>(v.z, v.w);
    float4 h;
    h.x = xop<M>(left, mxy); h.y = xop<M>(mxy, v.z);
    h.z = xop<M>(v.y, mzw);  h.w = xop<M>(mzw, right);
    return h;
}

template <bool M>
__device__ __forceinline__ void do_round(const float* __restrict__ s, float* __restrict__ dp,
                                         float* eL, float* eR, int tile) {
    const int tid = threadIdx.x;
    const int warp = tid >> 5, lane = tid & 31;
    const int r0 = tile * 8 - 4;
    const int col = warp * 128 + lane * 4;
    const float BND = M ? __int_as_float(0x7F800000) : __int_as_float(0xFF800000);

    float4 d[16];
#pragma unroll
    for (int i = 0; i < 16; i++) {
        int rr = r0 + i;
        if (rr >= 0 && rr < IMG) d[i] = *(const float4*)(s + (size_t)rr * IMG + col);
        else                     d[i] = make_float4(BND, BND, BND, BND);
    }

#pragma unroll
    for (int it = 0; it < 4; it++) {
        const int p = it & 1;
        if (lane == 0) {
#pragma unroll
            for (int i = 0; i < 16; i++) eL[((p * 4) + warp) * 16 + i] = d[i].x;
        } else if (lane == 31) {
#pragma unroll
            for (int i = 0; i < 16; i++) eR[((p * 4) + warp) * 16 + i] = d[i].w;
        }
        __syncthreads();

        const int lo = it + 1, hi = 14 - it;
        float4 hp = hpool16<M>(d[lo - 1], lo - 1, p, warp, lane, eL, eR, BND);
        float4 hc = hpool16<M>(d[lo],     lo,     p, warp, lane, eL, eR, BND);
#pragma unroll
        for (int r = lo; r <= hi; r++) {
            float4 hn = hpool16<M>(d[r + 1], r + 1, p, warp, lane, eL, eR, BND);
            d[r].x += xop3<M>(hp.x, hc.x, hn.x); d[r].y += xop3<M>(hp.y, hc.y, hn.y);
            d[r].z += xop3<M>(hp.z, hc.z, hn.z); d[r].w += xop3<M>(hp.w, hc.w, hn.w);
            hp = hc; hc = hn;
        }
    }

#pragma unroll
    for (int i = 4; i < 12; i++) {
        int rr = r0 + i;
        *(float4*)(dp + (size_t)rr * IMG + col) = d[i];
    }
}

// ---- head body (R4-proven): 2x4 pixels/thread, packed fma.rn.f32x2 ---------
__device__ __forceinline__ void do_head(const float* __restrict__ gm, const float* __restrict__ gx,
                                        float* __restrict__ outp, int hx,
                                        unsigned long long (*A2s)[18],
                                        unsigned long long* cb2s, float* w2s) {
    const int tid = threadIdx.x;
    const int tx = tid & 31, ty = tid >> 5;
    {
        const unsigned long long* A2g = (const unsigned long long*)(&HC.A2[0][0][0]);
        for (int i = tid; i < 32 * 18; i += 128) ((unsigned long long*)A2s)[i] = A2g[i];
        if (tid < 32) {
            cb2s[tid] = ((const unsigned long long*)HC.cb2)[tid];
            w2s[tid] = HC.w2[tid];
        }
    }
    __syncthreads();

    const int bx = hx & 7, by = hx >> 3;
    const int x0 = (bx * 32 + tx) * 2;
    const int y0 = (by * 4 + ty) * 4;
    const int xm2 = max(x0 - 2, 0);
    const int xp2 = min(x0 + 2, IMG - 2);

    unsigned long long tmin[6][3], tmax[6][3];
#pragma unroll
    for (int rr = 0; rr < 6; rr++) {
        int row = min(max(y0 + rr - 1, 0), IMG - 1);
        const float* pm = gm + (size_t)row * IMG;
        float2 L = *(const float2*)(pm + xm2);
        float2 Mv = *(const float2*)(pm + x0);
        float2 R = *(const float2*)(pm + xp2);
        tmin[rr][0] = pk2(L.y, Mv.x); tmin[rr][1] = pk2(Mv.x, Mv.y); tmin[rr][2] = pk2(Mv.y, R.x);
        const float* px = gx + (size_t)row * IMG;
        L = *(const float2*)(px + xm2);
        Mv = *(const float2*)(px + x0);
        R = *(const float2*)(px + xp2);
        tmax[rr][0] = pk2(L.y, Mv.x); tmax[rr][1] = pk2(Mv.x, Mv.y); tmax[rr][2] = pk2(Mv.y, R.x);
    }

    float accx[4] = {0.f, 0.f, 0.f, 0.f};
    float accy[4] = {0.f, 0.f, 0.f, 0.f};
#pragma unroll 2
    for (int j = 0; j < 32; j++) {
        unsigned long long u0 = cb2s[j], u1 = u0, u2 = u0, u3 = u0;
#pragma unroll
        for (int k = 0; k < 9; k++) {
            const int kh = k / 3, kw = k % 3;
            unsigned long long a = A2s[j][k];
            u0 = fma2(a, tmin[0 + kh][kw], u0);
            u1 = fma2(a, tmin[1 + kh][kw], u1);
            u2 = fma2(a, tmin[2 + kh][kw], u2);
            u3 = fma2(a, tmin[3 + kh][kw], u3);
        }
#pragma unroll
        for (int k = 0; k < 9; k++) {
            const int kh = k / 3, kw = k % 3;
            unsigned long long a = A2s[j][9 + k];
            u0 = fma2(a, tmax[0 + kh][kw], u0);
            u1 = fma2(a, tmax[1 + kh][kw], u1);
            u2 = fma2(a, tmax[2 + kh][kw], u2);
            u3 = fma2(a, tmax[3 + kh][kw], u3);
        }
        float w = w2s[j], lo, hi;
        upk2(u0, lo, hi);
        accx[0] = fmaf(w, fmaxf(lo, 0.f), accx[0]); accy[0] = fmaf(w, fmaxf(hi, 0.f), accy[0]);
        upk2(u1, lo, hi);
        accx[1] = fmaf(w, fmaxf(lo, 0.f), accx[1]); accy[1] = fmaf(w, fmaxf(hi, 0.f), accy[1]);
        upk2(u2, lo, hi);
        accx[2] = fmaf(w, fmaxf(lo, 0.f), accx[2]); accy[2] = fmaf(w, fmaxf(hi, 0.f), accy[2]);
        upk2(u3, lo, hi);
        accx[3] = fmaf(w, fmaxf(lo, 0.f), accx[3]); accy[3] = fmaf(w, fmaxf(hi, 0.f), accy[3]);
    }

    const float b2v = HC.b2;
#pragma unroll
    for (int i = 0; i < 4; i++) {
        float2 o;
        o.x = b2v + accx[i];
        o.y = b2v + accy[i];
        *(float2*)(outp + (size_t)(y0 + i) * IMG + x0) = o;
    }
}

// ---- border body: exact tap-gated recompute for the 1-pixel frame ----------
__device__ __forceinline__ void do_border(const float* __restrict__ gm, const float* __restrict__ gx,
                                          float* __restrict__ outp, int cta) {
    const int bi = cta * 128 + threadIdx.x;
    if (bi >= 2044) return;
    int x, y;
    if (bi < 512)        { y = 0;   x = bi; }
    else if (bi < 1024)  { y = 511; x = bi - 512; }
    else if (bi < 1534)  { x = 0;   y = bi - 1024 + 1; }
    else                 { x = 511; y = bi - 1534 + 1; }

    float vmn[9], vmx[9];
    bool valid[9];
#pragma unroll
    for (int k = 0; k < 9; k++) {
        int ty = y + k / 3 - 1, tx = x + k % 3 - 1;
        valid[k] = (ty >= 0 && ty < IMG && tx >= 0 && tx < IMG);
        size_t off = (size_t)min(max(ty, 0), IMG - 1) * IMG + (size_t)min(max(tx, 0), IMG - 1);
        vmn[k] = valid[k] ? gm[off] : 0.f;
        vmx[k] = valid[k] ? gx[off] : 0.f;
    }
    float acc = 0.f;
    for (int j = 0; j < 32; j++) {
        float u = HC.b1[j];
#pragma unroll
        for (int k = 0; k < 9; k++) {
            if (valid[k])
                u += HC.Amin[j][k] * vmn[k] + HC.Amax[j][k] * vmx[k] + HC.Bsum[j][k];
        }
        acc = fmaf(HC.w2[j], fmaxf(u, 0.f), acc);
    }
    outp[(size_t)y * IMG + x] = HC.b2 + acc;
}

// ---- megakernel: full DAG in one launch ------------------------------------
// Segment order (staggered for pipe overlap):
//   R(0) R(1) H(0) R(2) H(1) R(3) H(2) R(4) H(3) R(5) H(4) R(6) H(5) R(7) H(6) H(7)
// R segment = 512 CTAs (4 stages x 2 fields x 64 tiles); H = 272 (256 head + 16 border).
__global__ __launch_bounds__(128) void mega_kernel(const float* __restrict__ x,
                                                   float* __restrict__ minA,
                                                   float* __restrict__ minB,
                                                   float* __restrict__ maxA,
                                                   float* __restrict__ maxB,
                                                   float* __restrict__ out) {
    __shared__ float eL[2 * 4 * 16];
    __shared__ float eR[2 * 4 * 16];
    __shared__ unsigned long long A2s[32][18];
    __shared__ unsigned long long cb2s[32];
    __shared__ float w2s[32];

    const unsigned char segT[16] = {0,0,1,0,1,0,1,0,1,0,1,0,1,0,1,1};
    const unsigned char segI[16] = {0,1,0,2,1,3,2,4,3,5,4,6,5,7,6,7};
    int b = blockIdx.x;
    int k = 0;
#pragma unroll 1
    for (;;) {
        int sz = segT[k] ? 272 : 512;
        if (b < sz) break;
        b -= sz; ++k;
    }
    const int img = segI[k];
    const size_t ib = (size_t)img * NPIX;
    const int tid = threadIdx.x;

    if (segT[k] == 0) {
        // ---- round stage ----
        const int s = b >> 7;
        const int f = (b >> 6) & 1;
        const int tile = b & 63;
        if (s > 0) {
            if (tid == 0) {
                waitflag(&g_flag[img][s - 1][f][tile]);
                if (tile > 0)  waitflag(&g_flag[img][s - 1][f][tile - 1]);
                if (tile < 63) waitflag(&g_flag[img][s - 1][f][tile + 1]);
                __threadfence();
            }
            __syncthreads();
        }
        if (f == 0) {
            const float* src; float* dst;
            switch (s) {
                case 0:  src = x + ib;    dst = minA + ib; break;
                case 1:  src = minA + ib; dst = minB + ib; break;
                case 2:  src = minB + ib; dst = minA + ib; break;
                default: src = minA + ib; dst = minB + ib; break;
            }
            do_round<true>(src, dst, eL, eR, tile);
        } else {
            const float* src; float* dst;
            switch (s) {
                case 0:  src = x + ib;    dst = maxA + ib; break;
                case 1:  src = maxA + ib; dst = maxB + ib; break;
                case 2:  src = maxB + ib; dst = maxA + ib; break;
                default: src = maxA + ib; dst = maxB + ib; break;
            }
            do_round<false>(src, dst, eL, eR, tile);
        }
        __threadfence();
        __syncthreads();
        if (tid == 0) atomicExch(&g_flag[img][s][f][tile], 1);
    } else if (b < 256) {
        // ---- head ----
        const int by = b >> 3;
        if (tid == 0) {
            int t0 = max(2 * by - 1, 0), t1 = min(2 * by + 2, 63);
            for (int t = t0; t <= t1; ++t) {
                waitflag(&g_flag[img][3][0][t]);
                waitflag(&g_flag[img][3][1][t]);
            }
            __threadfence();
        }
        __syncthreads();
        do_head(minB + ib, maxB + ib, out + ib, b, A2s, cb2s, w2s);
        __threadfence();
        __syncthreads();
        if (tid == 0) atomicAdd(&g_headcnt[img], 1);
    } else {
        // ---- border (after ALL head CTAs of this image) ----
        if (tid == 0) {
            while (atomicAdd(&g_headcnt[img], 0) < 256) __nanosleep(128);
            __threadfence();
        }
        __syncthreads();
        do_border(minB + ib, maxB + ib, out + ib, b - 256);
    }
}

// ---------------------------------------------------------------------------
extern "C" void kernel_launch(void* const* d_in, const int* in_sizes, int n_in,
                              void* d_out, int out_size) {
    const float* x  = (const float*)d_in[0];
    const float* w0 = (const float*)d_in[1];
    const float* b0 = (const float*)d_in[2];
    const float* w1 = (const float*)d_in[3];
    const float* b1 = (const float*)d_in[4];
    const float* w2 = (const float*)d_in[5];
    const float* b2 = (const float*)d_in[6];
    float* out = (float*)d_out;

    static float *pMinA = nullptr, *pMinB = nullptr, *pMaxA = nullptr, *pMaxB = nullptr;
    if (!pMinA) {
        cudaGetSymbolAddress((void**)&pMinA, g_min_a);
        cudaGetSymbolAddress((void**)&pMinB, g_min_b);
        cudaGetSymbolAddress((void**)&pMaxA, g_max_a);
        cudaGetSymbolAddress((void**)&pMaxB, g_max_b);
    }

    prep_kernel<<<1, 512>>>(w0, b0, w1, b1, w2, b2);

    mega_kernel<<<6272, 128>>>(x, pMinA, pMinB, pMaxA, pMaxB, out);
}

// round 13
// speedup vs baseline: 1.6874x; 1.6874x over previous
#include <cuda_runtime.h>

#define NIMG 8
#define IMG  512
#define NPIX (IMG * IMG)

__device__ float g_min_a[NIMG * NPIX];
__device__ float g_min_b[NIMG * NPIX];
__device__ float g_max_a[NIMG * NPIX];
__device__ float g_max_b[NIMG * NPIX];

__device__ __forceinline__ float fmin3(float a, float b, float c) { return fminf(a, fminf(b, c)); }
__device__ __forceinline__ float fmax3(float a, float b, float c) { return fmaxf(a, fmaxf(b, c)); }

__device__ __forceinline__ unsigned long long pk2(float lo, float hi) {
    unsigned long long r;
    asm("mov.b64 %0, {%1, %2};" : "=l"(r) : "f"(lo), "f"(hi));
    return r;
}
__device__ __forceinline__ void upk2(unsigned long long v, float& lo, float& hi) {
    asm("mov.b64 {%0, %1}, %2;" : "=f"(lo), "=f"(hi) : "l"(v));
}
__device__ __forceinline__ unsigned long long fma2(unsigned long long a, unsigned long long b,
                                                   unsigned long long c) {
    unsigned long long d;
    asm("fma.rn.f32x2 %0, %1, %2, %3;" : "=l"(d) : "l"(a), "l"(b), "l"(c));
    return d;
}

// ---- round: R4-proven fused 4 iterations, 16 rows x 4 cols/thread ----------
template <bool M>
__device__ __forceinline__ float4 hpool16(float4 v, int r, int p, int warp, int lane,
                                          const float* eL, const float* eR, float BND) {
    float left  = __shfl_up_sync(0xffffffffu, v.w, 1);
    float right = __shfl_down_sync(0xffffffffu, v.x, 1);
    if (lane == 0)  left  = (warp == 0) ? BND : eR[((p * 4) + warp - 1) * 16 + r];
    if (lane == 31) right = (warp == 3) ? BND : eL[((p * 4) + warp + 1) * 16 + r];
    float4 h;
    if (M) {
        h.x = fmin3(left, v.x, v.y); h.y = fmin3(v.x, v.y, v.z);
        h.z = fmin3(v.y, v.z, v.w);  h.w = fmin3(v.z, v.w, right);
    } else {
        h.x = fmax3(left, v.x, v.y); h.y = fmax3(v.x, v.y, v.z);
        h.z = fmax3(v.y, v.z, v.w);  h.w = fmax3(v.z, v.w, right);
    }
    return h;
}

template <bool M>
__device__ __forceinline__ void do_round(const float* __restrict__ s, float* __restrict__ dp,
                                         float* eL, float* eR) {
    const int tid = threadIdx.x;
    const int warp = tid >> 5, lane = tid & 31;
    const int tile = blockIdx.x;
    const int r0 = tile * 8 - 4;
    const int col = warp * 128 + lane * 4;
    const float BND = M ? __int_as_float(0x7F800000) : __int_as_float(0xFF800000);

    float4 d[16];
#pragma unroll
    for (int i = 0; i < 16; i++) {
        int rr = r0 + i;
        if (rr >= 0 && rr < IMG) d[i] = *(const float4*)(s + (size_t)rr * IMG + col);
        else                     d[i] = make_float4(BND, BND, BND, BND);
    }

#pragma unroll
    for (int it = 0; it < 4; it++) {
        const int p = it & 1;
        if (lane == 0) {
#pragma unroll
            for (int i = 0; i < 16; i++) eL[((p * 4) + warp) * 16 + i] = d[i].x;
        } else if (lane == 31) {
#pragma unroll
            for (int i = 0; i < 16; i++) eR[((p * 4) + warp) * 16 + i] = d[i].w;
        }
        __syncthreads();

        const int lo = it + 1, hi = 14 - it;
        float4 hp = hpool16<M>(d[lo - 1], lo - 1, p, warp, lane, eL, eR, BND);
        float4 hc = hpool16<M>(d[lo],     lo,     p, warp, lane, eL, eR, BND);
#pragma unroll
        for (int r = lo; r <= hi; r++) {
            float4 hn = hpool16<M>(d[r + 1], r + 1, p, warp, lane, eL, eR, BND);
            if (M) {
                d[r].x += fmin3(hp.x, hc.x, hn.x); d[r].y += fmin3(hp.y, hc.y, hn.y);
                d[r].z += fmin3(hp.z, hc.z, hn.z); d[r].w += fmin3(hp.w, hc.w, hn.w);
            } else {
                d[r].x += fmax3(hp.x, hc.x, hn.x); d[r].y += fmax3(hp.y, hc.y, hn.y);
                d[r].z += fmax3(hp.z, hc.z, hn.z); d[r].w += fmax3(hp.w, hc.w, hn.w);
            }
            hp = hc; hc = hn;
        }
    }

#pragma unroll
    for (int i = 4; i < 12; i++) {
        int rr = r0 + i;
        *(float4*)(dp + (size_t)rr * IMG + col) = d[i];
    }
}

__global__ __launch_bounds__(128) void round_kernel(const float* __restrict__ srcMin,
                                                    const float* __restrict__ srcMax,
                                                    float* __restrict__ dstMin,
                                                    float* __restrict__ dstMax) {
    __shared__ float eL[2 * 4 * 16];
    __shared__ float eR[2 * 4 * 16];
    const size_t ib = (size_t)blockIdx.y * NPIX;
    if (blockIdx.z == 0) do_round<true>(srcMin + ib, dstMin + ib, eL, eR);
    else                 do_round<false>(srcMax + ib, dstMax + ib, eL, eR);
}

// ---- merged head + border, self-folding weights, race-free writes ----------
// grid (272, 1, NIMG): blockIdx.x < 256 -> interior head tile (masked writes),
//                      blockIdx.x >= 256 -> border ring pixels (exclusive owner).
__global__ __launch_bounds__(128) void head_kernel(const float* __restrict__ gmin,
                                                   const float* __restrict__ gmax,
                                                   const float* __restrict__ w0,
                                                   const float* __restrict__ b0,
                                                   const float* __restrict__ w1,
                                                   const float* __restrict__ b1,
                                                   const float* __restrict__ w2,
                                                   const float* __restrict__ b2,
                                                   float* __restrict__ out) {
    __shared__ float Amin[32][9], Amax[32][9], Bs[32][9];
    __shared__ unsigned long long A2s[32][18];
    __shared__ unsigned long long cb2s[32];
    __shared__ float w2s[32];
    __shared__ float b1s[32];

    const int tid = threadIdx.x;
    // ---- fold weights into smem (every CTA; inputs are L2-broadcast) ----
    {
        float w0r[8], b0r[8];
#pragma unroll
        for (int c = 0; c < 8; c++) { w0r[c] = w0[c]; b0r[c] = 65536.f * b0[c]; }
        for (int id = tid; id < 288; id += 128) {
            int j = id / 9, t = id % 9;
            float amin = 0.f, amax = 0.f, bs = 0.f;
#pragma unroll
            for (int c = 0; c < 8; c++) {
                float w = w1[j * 72 + c * 9 + t];
                if (w0r[c] >= 0.f) amin += w * w0r[c]; else amax += w * w0r[c];
                bs += w * b0r[c];
            }
            Amin[j][t] = amin; Amax[j][t] = amax; Bs[j][t] = bs;
            A2s[j][t]     = pk2(amin, amin);
            A2s[j][9 + t] = pk2(amax, amax);
        }
        if (tid < 32) { w2s[tid] = w2[tid]; b1s[tid] = b1[tid]; }
        __syncthreads();
        if (tid < 32) {
            float cb = b1s[tid];
#pragma unroll
            for (int t = 0; t < 9; t++) cb += Bs[tid][t];
            cb2s[tid] = pk2(cb, cb);
        }
        __syncthreads();
    }

    const int img = blockIdx.z;
    const size_t ib = (size_t)img * NPIX;
    const float* gm = gmin + ib;
    const float* gx = gmax + ib;
    float* outp = out + ib;
    const float b2v = b2[0];

    if (blockIdx.x < 256) {
        // ---- interior head: 2x4 pixels/thread, packed f32x2, masked writes ----
        const int tx = tid & 31, ty = tid >> 5;
        const int bx = blockIdx.x & 7, by = blockIdx.x >> 3;
        const int x0 = (bx * 32 + tx) * 2;
        const int y0 = (by * 4 + ty) * 4;
        const int xm2 = max(x0 - 2, 0);
        const int xp2 = min(x0 + 2, IMG - 2);

        unsigned long long tmin[6][3], tmax[6][3];
#pragma unroll
        for (int rr = 0; rr < 6; rr++) {
            int row = min(max(y0 + rr - 1, 0), IMG - 1);
            const float* pm = gm + (size_t)row * IMG;
            float2 L = *(const float2*)(pm + xm2);
            float2 Mv = *(const float2*)(pm + x0);
            float2 R = *(const float2*)(pm + xp2);
            tmin[rr][0] = pk2(L.y, Mv.x); tmin[rr][1] = pk2(Mv.x, Mv.y); tmin[rr][2] = pk2(Mv.y, R.x);
            const float* px = gx + (size_t)row * IMG;
            L = *(const float2*)(px + xm2);
            Mv = *(const float2*)(px + x0);
            R = *(const float2*)(px + xp2);
            tmax[rr][0] = pk2(L.y, Mv.x); tmax[rr][1] = pk2(Mv.x, Mv.y); tmax[rr][2] = pk2(Mv.y, R.x);
        }

        float accx[4] = {0.f, 0.f, 0.f, 0.f};
        float accy[4] = {0.f, 0.f, 0.f, 0.f};
#pragma unroll 2
        for (int j = 0; j < 32; j++) {
            unsigned long long u0 = cb2s[j], u1 = u0, u2 = u0, u3 = u0;
#pragma unroll
            for (int k = 0; k < 9; k++) {
                const int kh = k / 3, kw = k % 3;
                unsigned long long a = A2s[j][k];
                u0 = fma2(a, tmin[0 + kh][kw], u0);
                u1 = fma2(a, tmin[1 + kh][kw], u1);
                u2 = fma2(a, tmin[2 + kh][kw], u2);
                u3 = fma2(a, tmin[3 + kh][kw], u3);
            }
#pragma unroll
            for (int k = 0; k < 9; k++) {
                const int kh = k / 3, kw = k % 3;
                unsigned long long a = A2s[j][9 + k];
                u0 = fma2(a, tmax[0 + kh][kw], u0);
                u1 = fma2(a, tmax[1 + kh][kw], u1);
                u2 = fma2(a, tmax[2 + kh][kw], u2);
                u3 = fma2(a, tmax[3 + kh][kw], u3);
            }
            float w = w2s[j], lo, hi;
            upk2(u0, lo, hi);
            accx[0] = fmaf(w, fmaxf(lo, 0.f), accx[0]); accy[0] = fmaf(w, fmaxf(hi, 0.f), accy[0]);
            upk2(u1, lo, hi);
            accx[1] = fmaf(w, fmaxf(lo, 0.f), accx[1]); accy[1] = fmaf(w, fmaxf(hi, 0.f), accy[1]);
            upk2(u2, lo, hi);
            accx[2] = fmaf(w, fmaxf(lo, 0.f), accx[2]); accy[2] = fmaf(w, fmaxf(hi, 0.f), accy[2]);
            upk2(u3, lo, hi);
            accx[3] = fmaf(w, fmaxf(lo, 0.f), accx[3]); accy[3] = fmaf(w, fmaxf(hi, 0.f), accy[3]);
        }

#pragma unroll
        for (int i = 0; i < 4; i++) {
            int yy = y0 + i;
            if (yy == 0 || yy == IMG - 1) continue;       // ring rows owned by border
            float ox = b2v + accx[i];
            float oy = b2v + accy[i];
            if (x0 == 0)              outp[(size_t)yy * IMG + 1] = oy;        // x=0 is ring
            else if (x0 == IMG - 2)   outp[(size_t)yy * IMG + (IMG - 2)] = ox; // x=511 is ring
            else                      *(float2*)(outp + (size_t)yy * IMG + x0) = make_float2(ox, oy);
        }
    } else {
        // ---- border ring: exact tap-gated recompute ----
        const int bi = (blockIdx.x - 256) * 128 + tid;
        if (bi >= 2044) return;
        int x, y;
        if (bi < 512)        { y = 0;   x = bi; }
        else if (bi < 1024)  { y = 511; x = bi - 512; }
        else if (bi < 1534)  { x = 0;   y = bi - 1024 + 1; }
        else                 { x = 511; y = bi - 1534 + 1; }

        float vmn[9], vmx[9];
        bool valid[9];
#pragma unroll
        for (int k = 0; k < 9; k++) {
            int ty = y + k / 3 - 1, tx = x + k % 3 - 1;
            valid[k] = (ty >= 0 && ty < IMG && tx >= 0 && tx < IMG);
            size_t off = (size_t)min(max(ty, 0), IMG - 1) * IMG + (size_t)min(max(tx, 0), IMG - 1);
            vmn[k] = valid[k] ? gm[off] : 0.f;
            vmx[k] = valid[k] ? gx[off] : 0.f;
        }
        float acc = 0.f;
        for (int j = 0; j < 32; j++) {
            float u = b1s[j];
#pragma unroll
            for (int k = 0; k < 9; k++) {
                if (valid[k])
                    u += Amin[j][k] * vmn[k] + Amax[j][k] * vmx[k] + Bs[j][k];
            }
            acc = fmaf(w2s[j], fmaxf(u, 0.f), acc);
        }
        outp[(size_t)y * IMG + x] = b2v + acc;
    }
}

// ---------------------------------------------------------------------------
extern "C" void kernel_launch(void* const* d_in, const int* in_sizes, int n_in,
                              void* d_out, int out_size) {
    const float* x  = (const float*)d_in[0];
    const float* w0 = (const float*)d_in[1];
    const float* b0 = (const float*)d_in[2];
    const float* w1 = (const float*)d_in[3];
    const float* b1 = (const float*)d_in[4];
    const float* w2 = (const float*)d_in[5];
    const float* b2 = (const float*)d_in[6];
    float* out = (float*)d_out;

    static float *pMinA = nullptr, *pMinB = nullptr, *pMaxA = nullptr, *pMaxB = nullptr;
    if (!pMinA) {
        cudaGetSymbolAddress((void**)&pMinA, g_min_a);
        cudaGetSymbolAddress((void**)&pMinB, g_min_b);
        cudaGetSymbolAddress((void**)&pMaxA, g_max_a);
        cudaGetSymbolAddress((void**)&pMaxB, g_max_b);
    }

    dim3 rblk(128);
    dim3 rgrd(IMG / 8, NIMG, 2);
    round_kernel<<<rgrd, rblk>>>(x,     x,     pMinA, pMaxA);   // iters 1-4
    round_kernel<<<rgrd, rblk>>>(pMinA, pMaxA, pMinB, pMaxB);   // iters 5-8
    round_kernel<<<rgrd, rblk>>>(pMinB, pMaxB, pMinA, pMaxA);   // iters 9-12
    round_kernel<<<rgrd, rblk>>>(pMinA, pMaxA, pMinB, pMaxB);   // iters 13-16

    dim3 hgrd(272, 1, NIMG);
    head_kernel<<<hgrd, rblk>>>(pMinB, pMaxB, w0, b0, w1, b1, w2, b2, out);
}